// round 12
// baseline (speedup 1.0000x reference)
#include <cuda_runtime.h>
#include <cstdint>

#define NN   10000
#define EE   320000
#define GG   64
#define NIN  64
#define EIN  16
#define HID  256

// ---------------- scratch (device-side only; NEVER passed from host) ----------------
__device__ __align__(16) uint32_t g_W0ch[(HID / 2) * NIN];   // half2-packed we2@l0_lw: [kpair][n]
__device__ __align__(16) uint32_t g_W1ch[(HID / 2) * HID];   // half2-packed we2@l1_lw
__device__ __align__(16) float g_c0[NIN];
__device__ __align__(16) float g_c1[HID];
__device__ __align__(16) float g_agg0[NN * NIN];
__device__ __align__(16) float g_agg1[NN * HID];
__device__ __align__(16) float g_t0[NN * HID];
__device__ __align__(16) float g_x1[NN * HID];
__device__ __align__(16) float g_x2[NN * HID];
__device__ __align__(16) float g_psum[GG * HID];
__device__ float g_pcnt[GG];
__device__ int   g_is64;

// ---------------- helpers ----------------
__device__ __forceinline__ int load_idx(const void* p, long long i) {
    if (g_is64) return (int)((const long long*)p)[i];
    return ((const int*)p)[i];
}

__device__ __forceinline__ void red_add_v4(float* p, float a, float b, float c, float d) {
    asm volatile("red.global.add.v4.f32 [%0], {%1, %2, %3, %4};"
                 :: "l"(p), "f"(a), "f"(b), "f"(c), "f"(d) : "memory");
}

// pack two f32 into half2 (lo = first arg)
__device__ __forceinline__ uint32_t pack_h2(float lo, float hi) {
    uint32_t r;
    asm("cvt.rn.f16x2.f32 %0, %1, %2;" : "=r"(r) : "f"(hi), "f"(lo));
    return r;
}

// m16n8k16 f16 MMA, f32 accum, D += A*B
__device__ __forceinline__ void mma_f16(float* d,
    uint32_t a0, uint32_t a1, uint32_t a2, uint32_t a3,
    uint32_t b0, uint32_t b1)
{
    asm volatile(
        "mma.sync.aligned.m16n8k16.row.col.f32.f16.f16.f32 "
        "{%0,%1,%2,%3}, {%4,%5,%6,%7}, {%8,%9}, {%0,%1,%2,%3};"
        : "+f"(d[0]), "+f"(d[1]), "+f"(d[2]), "+f"(d[3])
        : "r"(a0), "r"(a1), "r"(a2), "r"(a3), "r"(b0), "r"(b1));
}

// zero scratch + detect index width (edge_mma<0> stays the 4th launch for ncu)
__global__ void zero_kernel(const long long* eidx) {
    int i = blockIdx.x * 256 + threadIdx.x;   // covers NN*HID = 2.56M exactly
    if (i < NN * NIN) g_agg0[i] = 0.f;
    if (i < NN * HID) g_agg1[i] = 0.f;
    if (i < GG * HID) g_psum[i] = 0.f;
    if (i < GG)       g_pcnt[i] = 0.f;
    if (i == 0) {
        int is64 = 1;
        #pragma unroll 1
        for (int k = 0; k < 64; k++) {
            long long v = eidx[k];
            if (v < 0 || v >= NN) { is64 = 0; break; }
        }
        g_is64 = is64;
    }
}

// ---------------- weight folding: Wch = half2(we2 @ lw), k-pair packed; c = be2@lw+lb ----
template<int LAYER>
__global__ __launch_bounds__(256) void prep_wc(const float* __restrict__ we2,
                                               const float* __restrict__ lw,
                                               const float* __restrict__ be2,
                                               const float* __restrict__ lb) {
    constexpr int COUT = (LAYER == 0) ? NIN : HID;
    uint32_t* wch = (LAYER == 0) ? g_W0ch : g_W1ch;
    float*    cv  = (LAYER == 0) ? g_c0   : g_c1;
    __shared__ float lw_s[32][256];
    __shared__ float we2_s[8][33];
    const int i0 = blockIdx.x * 8;   // 8 consecutive k rows (4 k-pairs)
    const int t = threadIdx.x;
    float acc[8];
    #pragma unroll
    for (int r = 0; r < 8; r++) acc[r] = 0.f;

    #pragma unroll 1
    for (int kc = 0; kc < HID; kc += 32) {
        __syncthreads();
        for (int i = t; i < 32 * COUT / 4; i += 256) {
            const int r = i / (COUT / 4), c = (i % (COUT / 4)) * 4;
            *(float4*)&lw_s[r][c] = __ldg((const float4*)&lw[(kc + r) * COUT + c]);
        }
        we2_s[t >> 5][t & 31] = we2[(i0 + (t >> 5)) * HID + kc + (t & 31)];
        __syncthreads();
        if (t < COUT) {
            #pragma unroll 4
            for (int k = 0; k < 32; k++) {
                const float wv = lw_s[k][t];
                #pragma unroll
                for (int r = 0; r < 8; r++) acc[r] = fmaf(we2_s[r][k], wv, acc[r]);
            }
        }
    }
    if (t < COUT) {
        #pragma unroll
        for (int j = 0; j < 4; j++)   // pack k-pairs
            wch[(i0 / 2 + j) * COUT + t] = pack_h2(acc[2 * j], acc[2 * j + 1]);
        if (blockIdx.x == 0) {
            float a = lb[t];
            #pragma unroll 4
            for (int k = 0; k < HID; k++) a = fmaf(be2[k], lw[k * COUT + t], a);
            cv[t] = a;
        }
    }
}

// ---------------- fused edge kernel, FP16 m16n8k16 mma.sync ----------------
// 64 edges / block, 8 warps. Phase1: h1 = relu(ea@we1+be1) (K=16, one mma/tile).
// Phase2: ep = h1@Wc, K=256 in 32-k chunks. All tensor operands half2-packed
// along k. ep staged f32, scatter via RED.128.
template<int LAYER>
__global__ __launch_bounds__(256) void edge_mma(
    const float* __restrict__ ea,
    const long long* __restrict__ eidx,
    const float* __restrict__ we1,
    const float* __restrict__ be1,
    const float* __restrict__ x_arg)
{
    constexpr int COUT = (LAYER == 0) ? NIN : HID;
    constexpr int EAS  = 12;          // ea row stride (half2 units); banks 12lq+lr distinct
    constexpr int H1S  = 132;         // h1 row stride (half2); banks 4lq+p distinct
    constexpr int SN1  = HID + 8;     // 264 (half2); 264%32==8 -> 8lr+lq distinct
    constexpr int SN2  = COUT + 8;    // 264 / 72, both %32==8
    constexpr int EPS  = COUT + 4;    // ep row stride (f32)
    constexpr int BS_U32 = (8 * SN1 > 16 * SN2) ? 8 * SN1 : 16 * SN2;
    // phase-2 warp tiling: layer1: 4 m-tiles x 4 n-tiles; layer0: 2 x 2 (8 warps = 2 mg x 4 ng)
    constexpr int MW  = (COUT == 256) ? 4 : 2;
    constexpr int NT2 = (COUT == 256) ? 4 : 2;

    const uint32_t* Wch = (LAYER == 0) ? g_W0ch : g_W1ch;
    const float* cvec   = (LAYER == 0) ? g_c0  : g_c1;
    const float* xin    = (LAYER == 0) ? x_arg : g_x1;
    float*       agg    = (LAYER == 0) ? g_agg0 : g_agg1;

    extern __shared__ char smraw[];
    uint32_t* ea_s = (uint32_t*)smraw;                 // 64*EAS u32
    uint32_t* h1_s = ea_s + 64 * EAS;                  // 64*H1S u32
    uint32_t* Bs   = h1_s + 64 * H1S;                  // BS_U32
    float*    ep_s = (float*)(Bs + BS_U32);            // 64*EPS f32
    float*    be1_s = ep_s + 64 * EPS;                 // HID
    float*    c_s   = be1_s + HID;                     // COUT
    int*      src_s = (int*)(c_s + COUT);              // 64
    int*      dst_s = src_s + 64;                      // 64

    const int t  = threadIdx.x;
    const long long e0 = (long long)blockIdx.x * 64;

    // ---- loads ----
    {   // ea: 64x16 f32 -> half2 pairs
        const int e = t >> 2, c = (t & 3) * 4;
        const float4 v = *(const float4*)&ea[(e0 + e) * EIN + c];
        ea_s[e * EAS + (c >> 1)]     = pack_h2(v.x, v.y);
        ea_s[e * EAS + (c >> 1) + 1] = pack_h2(v.z, v.w);
    }
    if (t < 64)       src_s[t]      = load_idx(eidx, e0 + t);
    else if (t < 128) dst_s[t - 64] = load_idx(eidx, (long long)EE + e0 + (t - 64));
    be1_s[t] = be1[t];
    if (t < COUT) c_s[t] = cvec[t];
    // we1 (16x256) -> Bs as [kpair][256] half2
    for (int i = t; i < 8 * HID; i += 256) {
        const int kp = i >> 8, n = i & 255;
        Bs[kp * SN1 + n] = pack_h2(__ldg(&we1[(2 * kp) * HID + n]),
                                   __ldg(&we1[(2 * kp + 1) * HID + n]));
    }
    __syncthreads();

    const int w  = t >> 5, l = t & 31;
    const int lq = l >> 2, lr = l & 3;

    float d[4][4][4];   // [m][nt][c]

    // ---- phase 1: h1 = relu(ea @ we1 + be1); every warp: 4 m-tiles x n-slice w*32 ----
    {
        const int n1 = w * 32;
        #pragma unroll
        for (int m = 0; m < 4; m++)
            #pragma unroll
            for (int nt = 0; nt < 4; nt++)
                { d[m][nt][0] = d[m][nt][1] = d[m][nt][2] = d[m][nt][3] = 0.f; }

        uint32_t bf[4][2];
        #pragma unroll
        for (int nt = 0; nt < 4; nt++) {
            const int n = n1 + nt * 8 + lq;
            bf[nt][0] = Bs[lr * SN1 + n];
            bf[nt][1] = Bs[(lr + 4) * SN1 + n];
        }
        #pragma unroll
        for (int m = 0; m < 4; m++) {
            const int row = m * 16 + lq;
            const uint32_t a0 = ea_s[row * EAS + lr];
            const uint32_t a1 = ea_s[(row + 8) * EAS + lr];
            const uint32_t a2 = ea_s[row * EAS + lr + 4];
            const uint32_t a3 = ea_s[(row + 8) * EAS + lr + 4];
            #pragma unroll
            for (int nt = 0; nt < 4; nt++)
                mma_f16(d[m][nt], a0, a1, a2, a3, bf[nt][0], bf[nt][1]);
        }
        // epilogue -> h1_s half2 (pair index = n/2)
        #pragma unroll
        for (int m = 0; m < 4; m++) {
            const int row = m * 16 + lq;
            #pragma unroll
            for (int nt = 0; nt < 4; nt++) {
                const int p = w * 16 + nt * 4 + lr;   // (n1 + nt*8 + 2lr)/2
                const float bv0 = be1_s[2 * p], bv1 = be1_s[2 * p + 1];
                h1_s[row * H1S + p] =
                    pack_h2(fmaxf(d[m][nt][0] + bv0, 0.f), fmaxf(d[m][nt][1] + bv1, 0.f));
                h1_s[(row + 8) * H1S + p] =
                    pack_h2(fmaxf(d[m][nt][2] + bv0, 0.f), fmaxf(d[m][nt][3] + bv1, 0.f));
            }
        }
    }

    // ---- phase 2: ep = h1 @ Wc, K=256 in 32-k chunks ----
    const int mg = (COUT == 256) ? 0 : (w & 1);
    const int n2 = (COUT == 256) ? w * 32 : (w >> 1) * 16;
    #pragma unroll
    for (int m = 0; m < MW; m++)
        #pragma unroll
        for (int nt = 0; nt < NT2; nt++)
            { d[m][nt][0] = d[m][nt][1] = d[m][nt][2] = d[m][nt][3] = 0.f; }

    #pragma unroll 1
    for (int kc = 0; kc < HID; kc += 32) {
        __syncthreads();   // prior Bs readers (phase1 / prev chunk) done; h1 writes visible
        for (int i = t; i < 16 * COUT / 4; i += 256) {
            const int r = i / (COUT / 4), c = (i % (COUT / 4)) * 4;
            *(uint4*)&Bs[r * SN2 + c] =
                *(const uint4*)&Wch[(size_t)(kc / 2 + r) * COUT + c];
        }
        __syncthreads();
        #pragma unroll
        for (int ks = 0; ks < 2; ks++) {
            uint32_t bf[NT2][2];
            #pragma unroll
            for (int nt = 0; nt < NT2; nt++) {
                const int n = n2 + nt * 8 + lq;
                bf[nt][0] = Bs[(ks * 8 + lr) * SN2 + n];
                bf[nt][1] = Bs[(ks * 8 + lr + 4) * SN2 + n];
            }
            const int pb = (kc >> 1) + ks * 8;
            #pragma unroll
            for (int m = 0; m < MW; m++) {
                const int row = mg * 32 + m * 16 + lq;
                const uint32_t a0 = h1_s[row * H1S + pb + lr];
                const uint32_t a1 = h1_s[(row + 8) * H1S + pb + lr];
                const uint32_t a2 = h1_s[row * H1S + pb + lr + 4];
                const uint32_t a3 = h1_s[(row + 8) * H1S + pb + lr + 4];
                #pragma unroll
                for (int nt = 0; nt < NT2; nt++)
                    mma_f16(d[m][nt], a0, a1, a2, a3, bf[nt][0], bf[nt][1]);
            }
        }
    }

    // stage ep (f32) and scatter
    #pragma unroll
    for (int m = 0; m < MW; m++) {
        const int row = mg * 32 + m * 16 + lq;
        #pragma unroll
        for (int nt = 0; nt < NT2; nt++) {
            const int n = n2 + nt * 8 + 2 * lr;
            *(float2*)&ep_s[row * EPS + n]       = make_float2(d[m][nt][0], d[m][nt][1]);
            *(float2*)&ep_s[(row + 8) * EPS + n] = make_float2(d[m][nt][2], d[m][nt][3]);
        }
    }
    __syncthreads();

    constexpr int CG = COUT / 4;
    for (int i = t; i < 64 * CG; i += 256) {
        const int e = i / CG, c = (i % CG) * 4;
        const float4 ep = *(const float4*)&ep_s[e * EPS + c];
        const float4 xv = __ldg((const float4*)&xin[(size_t)src_s[e] * COUT + c]);
        const float4 cv = *(const float4*)&c_s[c];
        red_add_v4(&agg[(size_t)dst_s[e] * COUT + c],
                   fmaxf(xv.x + ep.x + cv.x, 0.f),
                   fmaxf(xv.y + ep.y + cv.y, 0.f),
                   fmaxf(xv.z + ep.z + cv.z, 0.f),
                   fmaxf(xv.w + ep.w + cv.w, 0.f));
    }
}

template<int LAYER> struct EdgeSmem {
    static constexpr int COUT = (LAYER == 0) ? NIN : HID;
    static constexpr int SN2  = COUT + 8;
    static constexpr int BS_U32 = (8 * (HID + 8) > 16 * SN2) ? 8 * (HID + 8) : 16 * SN2;
    static constexpr int BYTES =
        (64 * 12 + 64 * 132 + BS_U32) * 4          // ea_s + h1_s + Bs (u32)
        + 64 * (COUT + 4) * 4                      // ep_s
        + HID * 4 + COUT * 4 + 128 * 4;            // be1_s + c_s + idx
};

// ---------------- node MLP (fp32 FMA): C = relu((A [+ A2]) @ W + b) ----------------
template<int MODE>
__global__ __launch_bounds__(256) void node_mlp(
    const float* __restrict__ x_arg,
    const float* __restrict__ W,
    const float* __restrict__ b)
{
    constexpr int  K   = (MODE == 0) ? NIN : HID;
    constexpr bool ADD = (MODE == 0) || (MODE == 2);
    const float* A  = (MODE == 0) ? x_arg :
                      (MODE == 2) ? g_x1  : g_t0;
    const float* A2 = (MODE == 0) ? g_agg0 : g_agg1;
    float*       C  = (MODE == 1) ? g_x1 :
                      (MODE == 3) ? g_x2 : g_t0;

    __shared__ float a_s[32][K + 4];
    const int t = threadIdx.x;
    const int r0 = blockIdx.x * 32;

    #pragma unroll 1
    for (int i = t; i < 32 * K; i += 256) {
        const int r = i / K, k = i % K;
        float v = 0.f;
        if (r0 + r < NN) {
            v = A[(size_t)(r0 + r) * K + k];
            if (ADD) v += A2[(size_t)(r0 + r) * K + k];
        }
        a_s[r][k] = v;
    }
    __syncthreads();

    const int j0 = (t % 64) * 4;
    const int rb = (t / 64) * 8;
    float acc[8][4];
    #pragma unroll
    for (int r = 0; r < 8; r++) { acc[r][0] = acc[r][1] = acc[r][2] = acc[r][3] = 0.f; }

    #pragma unroll 1
    for (int k = 0; k < K; k += 4) {
        const float4 w0 = __ldg((const float4*)&W[(k + 0) * HID + j0]);
        const float4 w1 = __ldg((const float4*)&W[(k + 1) * HID + j0]);
        const float4 w2 = __ldg((const float4*)&W[(k + 2) * HID + j0]);
        const float4 w3 = __ldg((const float4*)&W[(k + 3) * HID + j0]);
        #pragma unroll
        for (int r = 0; r < 8; r++) {
            const float4 a = *(const float4*)&a_s[rb + r][k];
            acc[r][0] = fmaf(a.x, w0.x, acc[r][0]);
            acc[r][1] = fmaf(a.x, w0.y, acc[r][1]);
            acc[r][2] = fmaf(a.x, w0.z, acc[r][2]);
            acc[r][3] = fmaf(a.x, w0.w, acc[r][3]);
            acc[r][0] = fmaf(a.y, w1.x, acc[r][0]);
            acc[r][1] = fmaf(a.y, w1.y, acc[r][1]);
            acc[r][2] = fmaf(a.y, w1.z, acc[r][2]);
            acc[r][3] = fmaf(a.y, w1.w, acc[r][3]);
            acc[r][0] = fmaf(a.z, w2.x, acc[r][0]);
            acc[r][1] = fmaf(a.z, w2.y, acc[r][1]);
            acc[r][2] = fmaf(a.z, w2.z, acc[r][2]);
            acc[r][3] = fmaf(a.z, w2.w, acc[r][3]);
            acc[r][0] = fmaf(a.w, w3.x, acc[r][0]);
            acc[r][1] = fmaf(a.w, w3.y, acc[r][1]);
            acc[r][2] = fmaf(a.w, w3.z, acc[r][2]);
            acc[r][3] = fmaf(a.w, w3.w, acc[r][3]);
        }
    }

    const float4 bv = __ldg((const float4*)&b[j0]);
    #pragma unroll
    for (int r = 0; r < 8; r++) {
        const int row = r0 + rb + r;
        if (row < NN) {
            float4 o;
            o.x = fmaxf(acc[r][0] + bv.x, 0.f);
            o.y = fmaxf(acc[r][1] + bv.y, 0.f);
            o.z = fmaxf(acc[r][2] + bv.z, 0.f);
            o.w = fmaxf(acc[r][3] + bv.w, 0.f);
            *(float4*)&C[(size_t)row * HID + j0] = o;
        }
    }
}

// ---------------- global mean pool ----------------
__global__ __launch_bounds__(256) void pool_sum(const long long* __restrict__ batch) {
    const long long idx = (long long)blockIdx.x * 256 + threadIdx.x;  // over N*HID/4
    if (idx < (long long)NN * HID / 4) {
        const int n = (int)(idx / (HID / 4));
        const int c = (int)(idx % (HID / 4)) * 4;
        const int g = load_idx(batch, n);
        const float4 v = *(const float4*)&g_x2[(size_t)n * HID + c];
        red_add_v4(&g_psum[g * HID + c], v.x, v.y, v.z, v.w);
        if (c == 0) atomicAdd(&g_pcnt[g], 1.0f);
    }
}

__global__ __launch_bounds__(256) void pool_final(float* __restrict__ out) {
    const int idx = blockIdx.x * 256 + threadIdx.x;  // G*HID = 16384
    const int g = idx >> 8;
    const float cnt = fmaxf(g_pcnt[g], 1.0f);
    out[idx] = g_psum[idx] / cnt;
}

// ---------------- launch ----------------
extern "C" void kernel_launch(void* const* d_in, const int* in_sizes, int n_in,
                              void* d_out, int out_size)
{
    const float*      x     = (const float*)d_in[0];
    const float*      ea    = (const float*)d_in[1];
    const long long*  eidx  = (const long long*)d_in[2];
    const long long*  batch = (const long long*)d_in[3];
    const float*      we1   = (const float*)d_in[4];
    const float*      be1   = (const float*)d_in[5];
    const float*      we2   = (const float*)d_in[6];
    const float*      be2   = (const float*)d_in[7];
    const float*      l0_lw = (const float*)d_in[8];
    const float*      l0_lb = (const float*)d_in[9];
    const float*      l0_w1 = (const float*)d_in[10];
    const float*      l0_b1 = (const float*)d_in[11];
    const float*      l0_w2 = (const float*)d_in[12];
    const float*      l0_b2 = (const float*)d_in[13];
    const float*      l1_lw = (const float*)d_in[14];
    const float*      l1_lb = (const float*)d_in[15];
    const float*      l1_w1 = (const float*)d_in[16];
    const float*      l1_b1 = (const float*)d_in[17];
    const float*      l1_w2 = (const float*)d_in[18];
    const float*      l1_b2 = (const float*)d_in[19];
    float* out = (float*)d_out;

    cudaFuncSetAttribute(edge_mma<0>, cudaFuncAttributeMaxDynamicSharedMemorySize,
                         EdgeSmem<0>::BYTES);
    cudaFuncSetAttribute(edge_mma<1>, cudaFuncAttributeMaxDynamicSharedMemorySize,
                         EdgeSmem<1>::BYTES);

    const int node_blocks = (NN + 31) / 32;

    // the 4th launch gets captured by ncu -> edge_mma<0>
    zero_kernel<<<NN * HID / 256, 256>>>(eidx);                     // 1
    prep_wc<0><<<HID / 8, 256>>>(we2, l0_lw, be2, l0_lb);           // 2
    prep_wc<1><<<HID / 8, 256>>>(we2, l1_lw, be2, l1_lb);           // 3

    // ---- layer 0 ----
    edge_mma<0><<<EE / 64, 256, EdgeSmem<0>::BYTES>>>(ea, eidx, we1, be1, x);   // 4
    node_mlp<0><<<node_blocks, 256>>>(x, l0_w1, l0_b1);
    node_mlp<1><<<node_blocks, 256>>>(nullptr, l0_w2, l0_b2);

    // ---- layer 1 ----
    edge_mma<1><<<EE / 64, 256, EdgeSmem<1>::BYTES>>>(ea, eidx, we1, be1, nullptr);
    node_mlp<2><<<node_blocks, 256>>>(nullptr, l1_w1, l1_b1);
    node_mlp<3><<<node_blocks, 256>>>(nullptr, l1_w2, l1_b2);

    // ---- global mean pool ----
    pool_sum<<<NN * HID / 4 / 256, 256>>>(batch);
    pool_final<<<GG * HID / 256, 256>>>(out);
}

// round 14
// speedup vs baseline: 1.3938x; 1.3938x over previous
#include <cuda_runtime.h>
#include <cuda_fp16.h>
#include <cstdint>

#define NN   10000
#define EE   320000
#define GG   64
#define NIN  64
#define EIN  16
#define HID  256

// ---------------- scratch (device-side only; NEVER passed from host) ----------------
__device__ __align__(16) uint32_t g_W0ch[(HID / 2) * NIN];   // half2-packed we2@l0_lw: [kpair][n]
__device__ __align__(16) uint32_t g_W1ch[(HID / 2) * HID];   // half2-packed we2@l1_lw
__device__ __align__(16) float g_c0[NIN];
__device__ __align__(16) float g_c1[HID];
__device__ __align__(16) float g_agg0[NN * NIN];
__device__ __align__(16) float g_agg1[NN * HID];
__device__ __align__(16) float g_t0[NN * HID];
__device__ __align__(16) float g_x1[NN * HID];
__device__ __align__(16) float g_x2[NN * HID];
__device__ __align__(16) float g_psum[GG * HID];
__device__ float g_pcnt[GG];
__device__ int   g_is64;

// ---------------- helpers ----------------
__device__ __forceinline__ int load_idx(const void* p, long long i) {
    if (g_is64) return (int)((const long long*)p)[i];
    return ((const int*)p)[i];
}

__device__ __forceinline__ void red_add_v4(float* p, float a, float b, float c, float d) {
    asm volatile("red.global.add.v4.f32 [%0], {%1, %2, %3, %4};"
                 :: "l"(p), "f"(a), "f"(b), "f"(c), "f"(d) : "memory");
}

// pack two f32 into half2 (lo = first arg)
__device__ __forceinline__ uint32_t pack_h2(float lo, float hi) {
    uint32_t r;
    asm("cvt.rn.f16x2.f32 %0, %1, %2;" : "=r"(r) : "f"(hi), "f"(lo));
    return r;
}

__device__ __forceinline__ float2 unpack_h2(uint32_t u) {
    return __half22float2(*reinterpret_cast<const __half2*>(&u));
}

// m16n8k16 f16 MMA, f32 accum, D += A*B
__device__ __forceinline__ void mma_f16(float* d,
    uint32_t a0, uint32_t a1, uint32_t a2, uint32_t a3,
    uint32_t b0, uint32_t b1)
{
    asm volatile(
        "mma.sync.aligned.m16n8k16.row.col.f32.f16.f16.f32 "
        "{%0,%1,%2,%3}, {%4,%5,%6,%7}, {%8,%9}, {%0,%1,%2,%3};"
        : "+f"(d[0]), "+f"(d[1]), "+f"(d[2]), "+f"(d[3])
        : "r"(a0), "r"(a1), "r"(a2), "r"(a3), "r"(b0), "r"(b1));
}

// zero scratch + detect index width (edge_mma<0> stays the 4th launch for ncu)
__global__ void zero_kernel(const long long* eidx) {
    int i = blockIdx.x * 256 + threadIdx.x;   // covers NN*HID = 2.56M exactly
    if (i < NN * NIN) g_agg0[i] = 0.f;
    if (i < NN * HID) g_agg1[i] = 0.f;
    if (i < GG * HID) g_psum[i] = 0.f;
    if (i < GG)       g_pcnt[i] = 0.f;
    if (i == 0) {
        int is64 = 1;
        #pragma unroll 1
        for (int k = 0; k < 64; k++) {
            long long v = eidx[k];
            if (v < 0 || v >= NN) { is64 = 0; break; }
        }
        g_is64 = is64;
    }
}

// ---------------- weight folding: Wch = half2(we2 @ lw), k-pair packed; c = be2@lw+lb ----
template<int LAYER>
__global__ __launch_bounds__(256) void prep_wc(const float* __restrict__ we2,
                                               const float* __restrict__ lw,
                                               const float* __restrict__ be2,
                                               const float* __restrict__ lb) {
    constexpr int COUT = (LAYER == 0) ? NIN : HID;
    uint32_t* wch = (LAYER == 0) ? g_W0ch : g_W1ch;
    float*    cv  = (LAYER == 0) ? g_c0   : g_c1;
    __shared__ float lw_s[32][256];
    __shared__ float we2_s[8][33];
    const int i0 = blockIdx.x * 8;   // 8 consecutive k rows (4 k-pairs)
    const int t = threadIdx.x;
    float acc[8];
    #pragma unroll
    for (int r = 0; r < 8; r++) acc[r] = 0.f;

    #pragma unroll 1
    for (int kc = 0; kc < HID; kc += 32) {
        __syncthreads();
        for (int i = t; i < 32 * COUT / 4; i += 256) {
            const int r = i / (COUT / 4), c = (i % (COUT / 4)) * 4;
            *(float4*)&lw_s[r][c] = __ldg((const float4*)&lw[(kc + r) * COUT + c]);
        }
        we2_s[t >> 5][t & 31] = we2[(i0 + (t >> 5)) * HID + kc + (t & 31)];
        __syncthreads();
        if (t < COUT) {
            #pragma unroll 4
            for (int k = 0; k < 32; k++) {
                const float wv = lw_s[k][t];
                #pragma unroll
                for (int r = 0; r < 8; r++) acc[r] = fmaf(we2_s[r][k], wv, acc[r]);
            }
        }
    }
    if (t < COUT) {
        #pragma unroll
        for (int j = 0; j < 4; j++)   // pack k-pairs
            wch[(i0 / 2 + j) * COUT + t] = pack_h2(acc[2 * j], acc[2 * j + 1]);
        if (blockIdx.x == 0) {
            float a = lb[t];
            #pragma unroll 4
            for (int k = 0; k < HID; k++) a = fmaf(be2[k], lw[k * COUT + t], a);
            cv[t] = a;
        }
    }
}

// ---------------- fused edge kernel, FP16 m16n8k16 mma.sync ----------------
// 64 edges / block, 8 warps. Phase1: h1 = relu(ea@we1+be1) (K=16, one mma/tile).
// Phase2: ep = h1@Wc, K=256 in 32-k chunks. After the k-loop, ep is staged as
// half2 INTO the h1 buffer (h1 dead by then) -> smem ~56KB, multi-CTA/SM.
template<int LAYER>
__global__ __launch_bounds__(256) void edge_mma(
    const float* __restrict__ ea,
    const long long* __restrict__ eidx,
    const float* __restrict__ we1,
    const float* __restrict__ be1,
    const float* __restrict__ x_arg)
{
    constexpr int COUT = (LAYER == 0) ? NIN : HID;
    constexpr int EAS  = 12;          // ea row stride (half2 units)
    constexpr int H1S  = 132;         // h1/ep row stride (half2)
    constexpr int SN1  = HID + 8;     // 264
    constexpr int SN2  = COUT + 8;    // 264 / 72
    constexpr int BS_U32 = (8 * SN1 > 16 * SN2) ? 8 * SN1 : 16 * SN2;
    constexpr int MW  = (COUT == 256) ? 4 : 2;
    constexpr int NT2 = (COUT == 256) ? 4 : 2;

    const uint32_t* Wch = (LAYER == 0) ? g_W0ch : g_W1ch;
    const float* cvec   = (LAYER == 0) ? g_c0  : g_c1;
    const float* xin    = (LAYER == 0) ? x_arg : g_x1;
    float*       agg    = (LAYER == 0) ? g_agg0 : g_agg1;

    extern __shared__ char smraw[];
    uint32_t* ea_s = (uint32_t*)smraw;                 // 64*EAS u32
    uint32_t* h1_s = ea_s + 64 * EAS;                  // 64*H1S u32 (h1, then ep)
    uint32_t* Bs   = h1_s + 64 * H1S;                  // BS_U32
    float*    be1_s = (float*)(Bs + BS_U32);           // HID
    float*    c_s   = be1_s + HID;                     // COUT
    int*      src_s = (int*)(c_s + COUT);              // 64
    int*      dst_s = src_s + 64;                      // 64

    const int t  = threadIdx.x;
    const long long e0 = (long long)blockIdx.x * 64;

    // ---- loads ----
    {   // ea: 64x16 f32 -> half2 pairs
        const int e = t >> 2, c = (t & 3) * 4;
        const float4 v = *(const float4*)&ea[(e0 + e) * EIN + c];
        ea_s[e * EAS + (c >> 1)]     = pack_h2(v.x, v.y);
        ea_s[e * EAS + (c >> 1) + 1] = pack_h2(v.z, v.w);
    }
    if (t < 64)       src_s[t]      = load_idx(eidx, e0 + t);
    else if (t < 128) dst_s[t - 64] = load_idx(eidx, (long long)EE + e0 + (t - 64));
    be1_s[t] = be1[t];
    if (t < COUT) c_s[t] = cvec[t];
    // we1 (16x256) -> Bs as [kpair][256] half2
    for (int i = t; i < 8 * HID; i += 256) {
        const int kp = i >> 8, n = i & 255;
        Bs[kp * SN1 + n] = pack_h2(__ldg(&we1[(2 * kp) * HID + n]),
                                   __ldg(&we1[(2 * kp + 1) * HID + n]));
    }
    __syncthreads();

    const int w  = t >> 5, l = t & 31;
    const int lq = l >> 2, lr = l & 3;

    float d[4][4][4];   // [m][nt][c]

    // ---- phase 1: h1 = relu(ea @ we1 + be1); every warp: 4 m-tiles x n-slice w*32 ----
    {
        #pragma unroll
        for (int m = 0; m < 4; m++)
            #pragma unroll
            for (int nt = 0; nt < 4; nt++)
                { d[m][nt][0] = d[m][nt][1] = d[m][nt][2] = d[m][nt][3] = 0.f; }

        uint32_t bf[4][2];
        #pragma unroll
        for (int nt = 0; nt < 4; nt++) {
            const int n = w * 32 + nt * 8 + lq;
            bf[nt][0] = Bs[lr * SN1 + n];
            bf[nt][1] = Bs[(lr + 4) * SN1 + n];
        }
        #pragma unroll
        for (int m = 0; m < 4; m++) {
            const int row = m * 16 + lq;
            const uint32_t a0 = ea_s[row * EAS + lr];
            const uint32_t a1 = ea_s[(row + 8) * EAS + lr];
            const uint32_t a2 = ea_s[row * EAS + lr + 4];
            const uint32_t a3 = ea_s[(row + 8) * EAS + lr + 4];
            #pragma unroll
            for (int nt = 0; nt < 4; nt++)
                mma_f16(d[m][nt], a0, a1, a2, a3, bf[nt][0], bf[nt][1]);
        }
        // epilogue -> h1_s half2 (pair index = n/2)
        #pragma unroll
        for (int m = 0; m < 4; m++) {
            const int row = m * 16 + lq;
            #pragma unroll
            for (int nt = 0; nt < 4; nt++) {
                const int p = w * 16 + nt * 4 + lr;
                const float bv0 = be1_s[2 * p], bv1 = be1_s[2 * p + 1];
                h1_s[row * H1S + p] =
                    pack_h2(fmaxf(d[m][nt][0] + bv0, 0.f), fmaxf(d[m][nt][1] + bv1, 0.f));
                h1_s[(row + 8) * H1S + p] =
                    pack_h2(fmaxf(d[m][nt][2] + bv0, 0.f), fmaxf(d[m][nt][3] + bv1, 0.f));
            }
        }
    }

    // ---- phase 2: ep = h1 @ Wc, K=256 in 32-k chunks ----
    const int mg = (COUT == 256) ? 0 : (w & 1);
    const int n2 = (COUT == 256) ? w * 32 : (w >> 1) * 16;
    #pragma unroll
    for (int m = 0; m < MW; m++)
        #pragma unroll
        for (int nt = 0; nt < NT2; nt++)
            { d[m][nt][0] = d[m][nt][1] = d[m][nt][2] = d[m][nt][3] = 0.f; }

    #pragma unroll 1
    for (int kc = 0; kc < HID; kc += 32) {
        __syncthreads();   // prior Bs readers (phase1 / prev chunk) done; h1 writes visible
        for (int i = t; i < 16 * COUT / 4; i += 256) {
            const int r = i / (COUT / 4), c = (i % (COUT / 4)) * 4;
            *(uint4*)&Bs[r * SN2 + c] =
                *(const uint4*)&Wch[(size_t)(kc / 2 + r) * COUT + c];
        }
        __syncthreads();
        #pragma unroll
        for (int ks = 0; ks < 2; ks++) {
            uint32_t bf[NT2][2];
            #pragma unroll
            for (int nt = 0; nt < NT2; nt++) {
                const int n = n2 + nt * 8 + lq;
                bf[nt][0] = Bs[(ks * 8 + lr) * SN2 + n];
                bf[nt][1] = Bs[(ks * 8 + lr + 4) * SN2 + n];
            }
            const int pb = (kc >> 1) + ks * 8;
            #pragma unroll
            for (int m = 0; m < MW; m++) {
                const int row = mg * 32 + m * 16 + lq;
                const uint32_t a0 = h1_s[row * H1S + pb + lr];
                const uint32_t a1 = h1_s[(row + 8) * H1S + pb + lr];
                const uint32_t a2 = h1_s[row * H1S + pb + lr + 4];
                const uint32_t a3 = h1_s[(row + 8) * H1S + pb + lr + 4];
                #pragma unroll
                for (int nt = 0; nt < NT2; nt++)
                    mma_f16(d[m][nt], a0, a1, a2, a3, bf[nt][0], bf[nt][1]);
            }
        }
    }

    __syncthreads();   // all h1 reads done; reuse h1_s as half2 ep storage
    #pragma unroll
    for (int m = 0; m < MW; m++) {
        const int row = mg * 32 + m * 16 + lq;
        #pragma unroll
        for (int nt = 0; nt < NT2; nt++) {
            const int p = (n2 >> 1) + nt * 4 + lr;   // (n2 + nt*8 + 2lr)/2
            h1_s[row * H1S + p]       = pack_h2(d[m][nt][0], d[m][nt][1]);
            h1_s[(row + 8) * H1S + p] = pack_h2(d[m][nt][2], d[m][nt][3]);
        }
    }
    __syncthreads();

    // ---- scatter: msg = relu(x[src] + ep + c) -> RED.128 into agg[dst] ----
    constexpr int CG = COUT / 4;
    for (int i = t; i < 64 * CG; i += 256) {
        const int e = i / CG, c = (i % CG) * 4;
        const float2 e01 = unpack_h2(h1_s[e * H1S + (c >> 1)]);
        const float2 e23 = unpack_h2(h1_s[e * H1S + (c >> 1) + 1]);
        const float4 xv = __ldg((const float4*)&xin[(size_t)src_s[e] * COUT + c]);
        const float4 cv = *(const float4*)&c_s[c];
        red_add_v4(&agg[(size_t)dst_s[e] * COUT + c],
                   fmaxf(xv.x + e01.x + cv.x, 0.f),
                   fmaxf(xv.y + e01.y + cv.y, 0.f),
                   fmaxf(xv.z + e23.x + cv.z, 0.f),
                   fmaxf(xv.w + e23.y + cv.w, 0.f));
    }
}

template<int LAYER> struct EdgeSmem {
    static constexpr int COUT = (LAYER == 0) ? NIN : HID;
    static constexpr int SN2  = COUT + 8;
    static constexpr int BS_U32 = (8 * (HID + 8) > 16 * SN2) ? 8 * (HID + 8) : 16 * SN2;
    static constexpr int BYTES =
        (64 * 12 + 64 * 132 + BS_U32) * 4          // ea_s + h1_s(+ep) + Bs
        + HID * 4 + COUT * 4 + 128 * 4;            // be1_s + c_s + idx
};

// ---------------- node MLP (fp32 FMA): C = relu((A [+ A2]) @ W + b) ----------------
template<int MODE>
__global__ __launch_bounds__(256) void node_mlp(
    const float* __restrict__ x_arg,
    const float* __restrict__ W,
    const float* __restrict__ b)
{
    constexpr int  K   = (MODE == 0) ? NIN : HID;
    constexpr bool ADD = (MODE == 0) || (MODE == 2);
    const float* A  = (MODE == 0) ? x_arg :
                      (MODE == 2) ? g_x1  : g_t0;
    const float* A2 = (MODE == 0) ? g_agg0 : g_agg1;
    float*       C  = (MODE == 1) ? g_x1 :
                      (MODE == 3) ? g_x2 : g_t0;

    __shared__ float a_s[32][K + 4];
    const int t = threadIdx.x;
    const int r0 = blockIdx.x * 32;

    #pragma unroll 1
    for (int i = t; i < 32 * K; i += 256) {
        const int r = i / K, k = i % K;
        float v = 0.f;
        if (r0 + r < NN) {
            v = A[(size_t)(r0 + r) * K + k];
            if (ADD) v += A2[(size_t)(r0 + r) * K + k];
        }
        a_s[r][k] = v;
    }
    __syncthreads();

    const int j0 = (t % 64) * 4;
    const int rb = (t / 64) * 8;
    float acc[8][4];
    #pragma unroll
    for (int r = 0; r < 8; r++) { acc[r][0] = acc[r][1] = acc[r][2] = acc[r][3] = 0.f; }

    #pragma unroll 1
    for (int k = 0; k < K; k += 4) {
        const float4 w0 = __ldg((const float4*)&W[(k + 0) * HID + j0]);
        const float4 w1 = __ldg((const float4*)&W[(k + 1) * HID + j0]);
        const float4 w2 = __ldg((const float4*)&W[(k + 2) * HID + j0]);
        const float4 w3 = __ldg((const float4*)&W[(k + 3) * HID + j0]);
        #pragma unroll
        for (int r = 0; r < 8; r++) {
            const float4 a = *(const float4*)&a_s[rb + r][k];
            acc[r][0] = fmaf(a.x, w0.x, acc[r][0]);
            acc[r][1] = fmaf(a.x, w0.y, acc[r][1]);
            acc[r][2] = fmaf(a.x, w0.z, acc[r][2]);
            acc[r][3] = fmaf(a.x, w0.w, acc[r][3]);
            acc[r][0] = fmaf(a.y, w1.x, acc[r][0]);
            acc[r][1] = fmaf(a.y, w1.y, acc[r][1]);
            acc[r][2] = fmaf(a.y, w1.z, acc[r][2]);
            acc[r][3] = fmaf(a.y, w1.w, acc[r][3]);
            acc[r][0] = fmaf(a.z, w2.x, acc[r][0]);
            acc[r][1] = fmaf(a.z, w2.y, acc[r][1]);
            acc[r][2] = fmaf(a.z, w2.z, acc[r][2]);
            acc[r][3] = fmaf(a.z, w2.w, acc[r][3]);
            acc[r][0] = fmaf(a.w, w3.x, acc[r][0]);
            acc[r][1] = fmaf(a.w, w3.y, acc[r][1]);
            acc[r][2] = fmaf(a.w, w3.z, acc[r][2]);
            acc[r][3] = fmaf(a.w, w3.w, acc[r][3]);
        }
    }

    const float4 bv = __ldg((const float4*)&b[j0]);
    #pragma unroll
    for (int r = 0; r < 8; r++) {
        const int row = r0 + rb + r;
        if (row < NN) {
            float4 o;
            o.x = fmaxf(acc[r][0] + bv.x, 0.f);
            o.y = fmaxf(acc[r][1] + bv.y, 0.f);
            o.z = fmaxf(acc[r][2] + bv.z, 0.f);
            o.w = fmaxf(acc[r][3] + bv.w, 0.f);
            *(float4*)&C[(size_t)row * HID + j0] = o;
        }
    }
}

// ---------------- global mean pool ----------------
__global__ __launch_bounds__(256) void pool_sum(const long long* __restrict__ batch) {
    const long long idx = (long long)blockIdx.x * 256 + threadIdx.x;  // over N*HID/4
    if (idx < (long long)NN * HID / 4) {
        const int n = (int)(idx / (HID / 4));
        const int c = (int)(idx % (HID / 4)) * 4;
        const int g = load_idx(batch, n);
        const float4 v = *(const float4*)&g_x2[(size_t)n * HID + c];
        red_add_v4(&g_psum[g * HID + c], v.x, v.y, v.z, v.w);
        if (c == 0) atomicAdd(&g_pcnt[g], 1.0f);
    }
}

__global__ __launch_bounds__(256) void pool_final(float* __restrict__ out) {
    const int idx = blockIdx.x * 256 + threadIdx.x;  // G*HID = 16384
    const int g = idx >> 8;
    const float cnt = fmaxf(g_pcnt[g], 1.0f);
    out[idx] = g_psum[idx] / cnt;
}

// ---------------- launch ----------------
extern "C" void kernel_launch(void* const* d_in, const int* in_sizes, int n_in,
                              void* d_out, int out_size)
{
    const float*      x     = (const float*)d_in[0];
    const float*      ea    = (const float*)d_in[1];
    const long long*  eidx  = (const long long*)d_in[2];
    const long long*  batch = (const long long*)d_in[3];
    const float*      we1   = (const float*)d_in[4];
    const float*      be1   = (const float*)d_in[5];
    const float*      we2   = (const float*)d_in[6];
    const float*      be2   = (const float*)d_in[7];
    const float*      l0_lw = (const float*)d_in[8];
    const float*      l0_lb = (const float*)d_in[9];
    const float*      l0_w1 = (const float*)d_in[10];
    const float*      l0_b1 = (const float*)d_in[11];
    const float*      l0_w2 = (const float*)d_in[12];
    const float*      l0_b2 = (const float*)d_in[13];
    const float*      l1_lw = (const float*)d_in[14];
    const float*      l1_lb = (const float*)d_in[15];
    const float*      l1_w1 = (const float*)d_in[16];
    const float*      l1_b1 = (const float*)d_in[17];
    const float*      l1_w2 = (const float*)d_in[18];
    const float*      l1_b2 = (const float*)d_in[19];
    float* out = (float*)d_out;

    cudaFuncSetAttribute(edge_mma<0>, cudaFuncAttributeMaxDynamicSharedMemorySize,
                         EdgeSmem<0>::BYTES);
    cudaFuncSetAttribute(edge_mma<1>, cudaFuncAttributeMaxDynamicSharedMemorySize,
                         EdgeSmem<1>::BYTES);

    const int node_blocks = (NN + 31) / 32;

    // the 4th launch gets captured by ncu -> edge_mma<0>
    zero_kernel<<<NN * HID / 256, 256>>>(eidx);                     // 1
    prep_wc<0><<<HID / 8, 256>>>(we2, l0_lw, be2, l0_lb);           // 2
    prep_wc<1><<<HID / 8, 256>>>(we2, l1_lw, be2, l1_lb);           // 3

    // ---- layer 0 ----
    edge_mma<0><<<EE / 64, 256, EdgeSmem<0>::BYTES>>>(ea, eidx, we1, be1, x);   // 4
    node_mlp<0><<<node_blocks, 256>>>(x, l0_w1, l0_b1);
    node_mlp<1><<<node_blocks, 256>>>(nullptr, l0_w2, l0_b2);

    // ---- layer 1 ----
    edge_mma<1><<<EE / 64, 256, EdgeSmem<1>::BYTES>>>(ea, eidx, we1, be1, nullptr);
    node_mlp<2><<<node_blocks, 256>>>(nullptr, l1_w1, l1_b1);
    node_mlp<3><<<node_blocks, 256>>>(nullptr, l1_w2, l1_b2);

    // ---- global mean pool ----
    pool_sum<<<NN * HID / 4 / 256, 256>>>(batch);
    pool_final<<<GG * HID / 256, 256>>>(out);
}

// round 15
// speedup vs baseline: 1.5675x; 1.1246x over previous
#include <cuda_runtime.h>
#include <cuda_fp16.h>
#include <cstdint>

#define NN   10000
#define EE   320000
#define GG   64
#define NIN  64
#define EIN  16
#define HID  256

// ---------------- scratch (device-side only; NEVER passed from host) ----------------
__device__ __align__(16) uint32_t g_W0ch[(HID / 2) * NIN];   // half2 we2@l0_lw [kpair][n]
__device__ __align__(16) uint32_t g_W1ch[(HID / 2) * HID];   // half2 we2@l1_lw
__device__ __align__(16) uint32_t g_Wp0[(NIN / 2) * HID];    // half2 l0_w1
__device__ __align__(16) uint32_t g_Wp1[(HID / 2) * HID];    // half2 l0_w2
__device__ __align__(16) uint32_t g_Wp2[(HID / 2) * HID];    // half2 l1_w1
__device__ __align__(16) uint32_t g_Wp3[(HID / 2) * HID];    // half2 l1_w2
__device__ __align__(16) float g_c0[NIN];
__device__ __align__(16) float g_c1[HID];
__device__ __align__(16) float g_agg0[NN * NIN];
__device__ __align__(16) float g_agg1[NN * HID];
__device__ __align__(16) float g_t0[NN * HID];
__device__ __align__(16) float g_x1[NN * HID];
__device__ __align__(16) float g_x2[NN * HID];
__device__ __align__(16) float g_psum[GG * HID];
__device__ float g_pcnt[GG];
__device__ int   g_is64;

// ---------------- helpers ----------------
__device__ __forceinline__ int load_idx(const void* p, long long i) {
    if (g_is64) return (int)((const long long*)p)[i];
    return ((const int*)p)[i];
}

__device__ __forceinline__ void red_add_v4(float* p, float a, float b, float c, float d) {
    asm volatile("red.global.add.v4.f32 [%0], {%1, %2, %3, %4};"
                 :: "l"(p), "f"(a), "f"(b), "f"(c), "f"(d) : "memory");
}

__device__ __forceinline__ uint32_t pack_h2(float lo, float hi) {
    uint32_t r;
    asm("cvt.rn.f16x2.f32 %0, %1, %2;" : "=r"(r) : "f"(hi), "f"(lo));
    return r;
}

__device__ __forceinline__ float2 unpack_h2(uint32_t u) {
    return __half22float2(*reinterpret_cast<const __half2*>(&u));
}

// m16n8k16 f16 MMA, f32 accum, D += A*B
__device__ __forceinline__ void mma_f16(float* d,
    uint32_t a0, uint32_t a1, uint32_t a2, uint32_t a3,
    uint32_t b0, uint32_t b1)
{
    asm volatile(
        "mma.sync.aligned.m16n8k16.row.col.f32.f16.f16.f32 "
        "{%0,%1,%2,%3}, {%4,%5,%6,%7}, {%8,%9}, {%0,%1,%2,%3};"
        : "+f"(d[0]), "+f"(d[1]), "+f"(d[2]), "+f"(d[3])
        : "r"(a0), "r"(a1), "r"(a2), "r"(a3), "r"(b0), "r"(b1));
}

// zero scratch + detect index width + half2-pack node-MLP weights
// (stays launch #1 so edge_mma<0> is the 4th launch, which ncu captures)
__global__ void zero_kernel(const long long* eidx,
                            const float* __restrict__ w0, const float* __restrict__ w1,
                            const float* __restrict__ w2, const float* __restrict__ w3) {
    int i = blockIdx.x * 256 + threadIdx.x;   // covers NN*HID = 2.56M
    if (i < NN * NIN) g_agg0[i] = 0.f;
    if (i < NN * HID) g_agg1[i] = 0.f;
    if (i < GG * HID) g_psum[i] = 0.f;
    if (i < GG)       g_pcnt[i] = 0.f;
    if (i < (NIN / 2) * HID) {
        const int kp = i >> 8, n = i & 255;
        g_Wp0[i] = pack_h2(w0[(2 * kp) * HID + n], w0[(2 * kp + 1) * HID + n]);
    }
    if (i < (HID / 2) * HID) {
        const int kp = i >> 8, n = i & 255;
        g_Wp1[i] = pack_h2(w1[(2 * kp) * HID + n], w1[(2 * kp + 1) * HID + n]);
        g_Wp2[i] = pack_h2(w2[(2 * kp) * HID + n], w2[(2 * kp + 1) * HID + n]);
        g_Wp3[i] = pack_h2(w3[(2 * kp) * HID + n], w3[(2 * kp + 1) * HID + n]);
    }
    if (i == 0) {
        int is64 = 1;
        #pragma unroll 1
        for (int k = 0; k < 64; k++) {
            long long v = eidx[k];
            if (v < 0 || v >= NN) { is64 = 0; break; }
        }
        g_is64 = is64;
    }
}

// ---------------- weight folding: Wch = half2(we2 @ lw), k-pair packed; c = be2@lw+lb ----
template<int LAYER>
__global__ __launch_bounds__(256) void prep_wc(const float* __restrict__ we2,
                                               const float* __restrict__ lw,
                                               const float* __restrict__ be2,
                                               const float* __restrict__ lb) {
    constexpr int COUT = (LAYER == 0) ? NIN : HID;
    uint32_t* wch = (LAYER == 0) ? g_W0ch : g_W1ch;
    float*    cv  = (LAYER == 0) ? g_c0   : g_c1;
    __shared__ float lw_s[32][256];
    __shared__ float we2_s[8][33];
    const int i0 = blockIdx.x * 8;
    const int t = threadIdx.x;
    float acc[8];
    #pragma unroll
    for (int r = 0; r < 8; r++) acc[r] = 0.f;

    #pragma unroll 1
    for (int kc = 0; kc < HID; kc += 32) {
        __syncthreads();
        for (int i = t; i < 32 * COUT / 4; i += 256) {
            const int r = i / (COUT / 4), c = (i % (COUT / 4)) * 4;
            *(float4*)&lw_s[r][c] = __ldg((const float4*)&lw[(kc + r) * COUT + c]);
        }
        we2_s[t >> 5][t & 31] = we2[(i0 + (t >> 5)) * HID + kc + (t & 31)];
        __syncthreads();
        if (t < COUT) {
            #pragma unroll 4
            for (int k = 0; k < 32; k++) {
                const float wv = lw_s[k][t];
                #pragma unroll
                for (int r = 0; r < 8; r++) acc[r] = fmaf(we2_s[r][k], wv, acc[r]);
            }
        }
    }
    if (t < COUT) {
        #pragma unroll
        for (int j = 0; j < 4; j++)
            wch[(i0 / 2 + j) * COUT + t] = pack_h2(acc[2 * j], acc[2 * j + 1]);
        if (blockIdx.x == 0) {
            float a = lb[t];
            #pragma unroll 4
            for (int k = 0; k < HID; k++) a = fmaf(be2[k], lw[k * COUT + t], a);
            cv[t] = a;
        }
    }
}

// ---------------- fused edge kernel, FP16 m16n8k16 mma.sync (R14 winner, unchanged) ----
template<int LAYER>
__global__ __launch_bounds__(256) void edge_mma(
    const float* __restrict__ ea,
    const long long* __restrict__ eidx,
    const float* __restrict__ we1,
    const float* __restrict__ be1,
    const float* __restrict__ x_arg)
{
    constexpr int COUT = (LAYER == 0) ? NIN : HID;
    constexpr int EAS  = 12;
    constexpr int H1S  = 132;
    constexpr int SN1  = HID + 8;
    constexpr int SN2  = COUT + 8;
    constexpr int BS_U32 = (8 * SN1 > 16 * SN2) ? 8 * SN1 : 16 * SN2;
    constexpr int MW  = (COUT == 256) ? 4 : 2;
    constexpr int NT2 = (COUT == 256) ? 4 : 2;

    const uint32_t* Wch = (LAYER == 0) ? g_W0ch : g_W1ch;
    const float* cvec   = (LAYER == 0) ? g_c0  : g_c1;
    const float* xin    = (LAYER == 0) ? x_arg : g_x1;
    float*       agg    = (LAYER == 0) ? g_agg0 : g_agg1;

    extern __shared__ char smraw[];
    uint32_t* ea_s = (uint32_t*)smraw;
    uint32_t* h1_s = ea_s + 64 * EAS;
    uint32_t* Bs   = h1_s + 64 * H1S;
    float*    be1_s = (float*)(Bs + BS_U32);
    float*    c_s   = be1_s + HID;
    int*      src_s = (int*)(c_s + COUT);
    int*      dst_s = src_s + 64;

    const int t  = threadIdx.x;
    const long long e0 = (long long)blockIdx.x * 64;

    {
        const int e = t >> 2, c = (t & 3) * 4;
        const float4 v = *(const float4*)&ea[(e0 + e) * EIN + c];
        ea_s[e * EAS + (c >> 1)]     = pack_h2(v.x, v.y);
        ea_s[e * EAS + (c >> 1) + 1] = pack_h2(v.z, v.w);
    }
    if (t < 64)       src_s[t]      = load_idx(eidx, e0 + t);
    else if (t < 128) dst_s[t - 64] = load_idx(eidx, (long long)EE + e0 + (t - 64));
    be1_s[t] = be1[t];
    if (t < COUT) c_s[t] = cvec[t];
    for (int i = t; i < 8 * HID; i += 256) {
        const int kp = i >> 8, n = i & 255;
        Bs[kp * SN1 + n] = pack_h2(__ldg(&we1[(2 * kp) * HID + n]),
                                   __ldg(&we1[(2 * kp + 1) * HID + n]));
    }
    __syncthreads();

    const int w  = t >> 5, l = t & 31;
    const int lq = l >> 2, lr = l & 3;

    float d[4][4][4];

    {
        #pragma unroll
        for (int m = 0; m < 4; m++)
            #pragma unroll
            for (int nt = 0; nt < 4; nt++)
                { d[m][nt][0] = d[m][nt][1] = d[m][nt][2] = d[m][nt][3] = 0.f; }

        uint32_t bf[4][2];
        #pragma unroll
        for (int nt = 0; nt < 4; nt++) {
            const int n = w * 32 + nt * 8 + lq;
            bf[nt][0] = Bs[lr * SN1 + n];
            bf[nt][1] = Bs[(lr + 4) * SN1 + n];
        }
        #pragma unroll
        for (int m = 0; m < 4; m++) {
            const int row = m * 16 + lq;
            const uint32_t a0 = ea_s[row * EAS + lr];
            const uint32_t a1 = ea_s[(row + 8) * EAS + lr];
            const uint32_t a2 = ea_s[row * EAS + lr + 4];
            const uint32_t a3 = ea_s[(row + 8) * EAS + lr + 4];
            #pragma unroll
            for (int nt = 0; nt < 4; nt++)
                mma_f16(d[m][nt], a0, a1, a2, a3, bf[nt][0], bf[nt][1]);
        }
        #pragma unroll
        for (int m = 0; m < 4; m++) {
            const int row = m * 16 + lq;
            #pragma unroll
            for (int nt = 0; nt < 4; nt++) {
                const int p = w * 16 + nt * 4 + lr;
                const float bv0 = be1_s[2 * p], bv1 = be1_s[2 * p + 1];
                h1_s[row * H1S + p] =
                    pack_h2(fmaxf(d[m][nt][0] + bv0, 0.f), fmaxf(d[m][nt][1] + bv1, 0.f));
                h1_s[(row + 8) * H1S + p] =
                    pack_h2(fmaxf(d[m][nt][2] + bv0, 0.f), fmaxf(d[m][nt][3] + bv1, 0.f));
            }
        }
    }

    const int mg = (COUT == 256) ? 0 : (w & 1);
    const int n2 = (COUT == 256) ? w * 32 : (w >> 1) * 16;
    #pragma unroll
    for (int m = 0; m < MW; m++)
        #pragma unroll
        for (int nt = 0; nt < NT2; nt++)
            { d[m][nt][0] = d[m][nt][1] = d[m][nt][2] = d[m][nt][3] = 0.f; }

    #pragma unroll 1
    for (int kc = 0; kc < HID; kc += 32) {
        __syncthreads();
        for (int i = t; i < 16 * COUT / 4; i += 256) {
            const int r = i / (COUT / 4), c = (i % (COUT / 4)) * 4;
            *(uint4*)&Bs[r * SN2 + c] =
                *(const uint4*)&Wch[(size_t)(kc / 2 + r) * COUT + c];
        }
        __syncthreads();
        #pragma unroll
        for (int ks = 0; ks < 2; ks++) {
            uint32_t bf[NT2][2];
            #pragma unroll
            for (int nt = 0; nt < NT2; nt++) {
                const int n = n2 + nt * 8 + lq;
                bf[nt][0] = Bs[(ks * 8 + lr) * SN2 + n];
                bf[nt][1] = Bs[(ks * 8 + lr + 4) * SN2 + n];
            }
            const int pb = (kc >> 1) + ks * 8;
            #pragma unroll
            for (int m = 0; m < MW; m++) {
                const int row = mg * 32 + m * 16 + lq;
                const uint32_t a0 = h1_s[row * H1S + pb + lr];
                const uint32_t a1 = h1_s[(row + 8) * H1S + pb + lr];
                const uint32_t a2 = h1_s[row * H1S + pb + lr + 4];
                const uint32_t a3 = h1_s[(row + 8) * H1S + pb + lr + 4];
                #pragma unroll
                for (int nt = 0; nt < NT2; nt++)
                    mma_f16(d[m][nt], a0, a1, a2, a3, bf[nt][0], bf[nt][1]);
            }
        }
    }

    __syncthreads();
    #pragma unroll
    for (int m = 0; m < MW; m++) {
        const int row = mg * 32 + m * 16 + lq;
        #pragma unroll
        for (int nt = 0; nt < NT2; nt++) {
            const int p = (n2 >> 1) + nt * 4 + lr;
            h1_s[row * H1S + p]       = pack_h2(d[m][nt][0], d[m][nt][1]);
            h1_s[(row + 8) * H1S + p] = pack_h2(d[m][nt][2], d[m][nt][3]);
        }
    }
    __syncthreads();

    constexpr int CG = COUT / 4;
    for (int i = t; i < 64 * CG; i += 256) {
        const int e = i / CG, c = (i % CG) * 4;
        const float2 e01 = unpack_h2(h1_s[e * H1S + (c >> 1)]);
        const float2 e23 = unpack_h2(h1_s[e * H1S + (c >> 1) + 1]);
        const float4 xv = __ldg((const float4*)&xin[(size_t)src_s[e] * COUT + c]);
        const float4 cv = *(const float4*)&c_s[c];
        red_add_v4(&agg[(size_t)dst_s[e] * COUT + c],
                   fmaxf(xv.x + e01.x + cv.x, 0.f),
                   fmaxf(xv.y + e01.y + cv.y, 0.f),
                   fmaxf(xv.z + e23.x + cv.z, 0.f),
                   fmaxf(xv.w + e23.y + cv.w, 0.f));
    }
}

template<int LAYER> struct EdgeSmem {
    static constexpr int COUT = (LAYER == 0) ? NIN : HID;
    static constexpr int SN2  = COUT + 8;
    static constexpr int BS_U32 = (8 * (HID + 8) > 16 * SN2) ? 8 * (HID + 8) : 16 * SN2;
    static constexpr int BYTES =
        (64 * 12 + 64 * 132 + BS_U32) * 4
        + HID * 4 + COUT * 4 + 128 * 4;
};

// ---------------- node MLP via FP16 MMA: C = relu((A [+ A2]) @ W + b) ----------------
// 64 rows/block, 8 warps x 32-col n-slices (same audited pattern as edge phase 2).
// MODE 0: A=x (K=64) +g_agg0 -> g_t0 ; MODE 1: A=g_t0 -> g_x1
// MODE 2: A=g_x1 +g_agg1 -> g_t0     ; MODE 3: A=g_t0 -> g_x2
template<int MODE>
__global__ __launch_bounds__(256) void node_mma(
    const float* __restrict__ x_arg,
    const float* __restrict__ b)
{
    constexpr int  K   = (MODE == 0) ? NIN : HID;
    constexpr bool ADD = (MODE == 0) || (MODE == 2);
    constexpr int  KP  = K / 2;
    constexpr int  AS  = KP + 4;     // 132 or 36; bank = 4lq+lr+const, conflict-free
    constexpr int  SN  = HID + 8;    // 264
    const float* A  = (MODE == 0) ? x_arg :
                      (MODE == 2) ? g_x1  : g_t0;
    const float* A2 = (MODE == 0) ? g_agg0 : g_agg1;
    const uint32_t* Wp = (MODE == 0) ? g_Wp0 : (MODE == 1) ? g_Wp1 :
                         (MODE == 2) ? g_Wp2 : g_Wp3;
    float*       C  = (MODE == 1) ? g_x1 :
                      (MODE == 3) ? g_x2 : g_t0;

    extern __shared__ char smraw[];
    uint32_t* a_s = (uint32_t*)smraw;          // 64*AS
    uint32_t* Bs  = a_s + 64 * AS;             // 16*SN
    float*    b_s = (float*)(Bs + 16 * SN);    // HID

    const int t  = threadIdx.x;
    const int r0 = blockIdx.x * 64;

    // load A (+A2) as f32, pack half2 pairs along k
    for (int i = t; i < 64 * K / 4; i += 256) {
        const int r = i / (K / 4), c = (i % (K / 4)) * 4;
        float4 v = make_float4(0.f, 0.f, 0.f, 0.f);
        if (r0 + r < NN) {
            v = *(const float4*)&A[(size_t)(r0 + r) * K + c];
            if (ADD) {
                const float4 u = *(const float4*)&A2[(size_t)(r0 + r) * K + c];
                v.x += u.x; v.y += u.y; v.z += u.z; v.w += u.w;
            }
        }
        a_s[r * AS + (c >> 1)]     = pack_h2(v.x, v.y);
        a_s[r * AS + (c >> 1) + 1] = pack_h2(v.z, v.w);
    }
    b_s[t] = b[t];
    __syncthreads();

    const int w  = t >> 5, l = t & 31;
    const int lq = l >> 2, lr = l & 3;

    float d[4][4][4];
    #pragma unroll
    for (int m = 0; m < 4; m++)
        #pragma unroll
        for (int nt = 0; nt < 4; nt++)
            { d[m][nt][0] = d[m][nt][1] = d[m][nt][2] = d[m][nt][3] = 0.f; }

    #pragma unroll 1
    for (int kc = 0; kc < K; kc += 32) {
        __syncthreads();
        for (int i = t; i < 16 * HID / 4; i += 256) {
            const int r = i / 64, c = (i % 64) * 4;
            *(uint4*)&Bs[r * SN + c] = *(const uint4*)&Wp[(size_t)(kc / 2 + r) * HID + c];
        }
        __syncthreads();
        #pragma unroll
        for (int ks = 0; ks < 2; ks++) {
            uint32_t bf[4][2];
            #pragma unroll
            for (int nt = 0; nt < 4; nt++) {
                const int n = w * 32 + nt * 8 + lq;
                bf[nt][0] = Bs[(ks * 8 + lr) * SN + n];
                bf[nt][1] = Bs[(ks * 8 + lr + 4) * SN + n];
            }
            const int pb = (kc >> 1) + ks * 8;
            #pragma unroll
            for (int m = 0; m < 4; m++) {
                const int row = m * 16 + lq;
                const uint32_t a0 = a_s[row * AS + pb + lr];
                const uint32_t a1 = a_s[(row + 8) * AS + pb + lr];
                const uint32_t a2 = a_s[row * AS + pb + lr + 4];
                const uint32_t a3 = a_s[(row + 8) * AS + pb + lr + 4];
                #pragma unroll
                for (int nt = 0; nt < 4; nt++)
                    mma_f16(d[m][nt], a0, a1, a2, a3, bf[nt][0], bf[nt][1]);
            }
        }
    }

    // epilogue: bias + relu (outer relu of the conv applies in all modes), f32 stores
    #pragma unroll
    for (int m = 0; m < 4; m++) {
        #pragma unroll
        for (int nt = 0; nt < 4; nt++) {
            const int n = w * 32 + nt * 8 + 2 * lr;
            const float bv0 = b_s[n], bv1 = b_s[n + 1];
            const int row0 = r0 + m * 16 + lq;
            const int row1 = row0 + 8;
            if (row0 < NN)
                *(float2*)&C[(size_t)row0 * HID + n] =
                    make_float2(fmaxf(d[m][nt][0] + bv0, 0.f), fmaxf(d[m][nt][1] + bv1, 0.f));
            if (row1 < NN)
                *(float2*)&C[(size_t)row1 * HID + n] =
                    make_float2(fmaxf(d[m][nt][2] + bv0, 0.f), fmaxf(d[m][nt][3] + bv1, 0.f));
        }
    }
}

template<int MODE> struct NodeSmem {
    static constexpr int K  = (MODE == 0) ? NIN : HID;
    static constexpr int AS = K / 2 + 4;
    static constexpr int BYTES = (64 * AS + 16 * (HID + 8)) * 4 + HID * 4;
};

// ---------------- global mean pool ----------------
__global__ __launch_bounds__(256) void pool_sum(const long long* __restrict__ batch) {
    const long long idx = (long long)blockIdx.x * 256 + threadIdx.x;
    if (idx < (long long)NN * HID / 4) {
        const int n = (int)(idx / (HID / 4));
        const int c = (int)(idx % (HID / 4)) * 4;
        const int g = load_idx(batch, n);
        const float4 v = *(const float4*)&g_x2[(size_t)n * HID + c];
        red_add_v4(&g_psum[g * HID + c], v.x, v.y, v.z, v.w);
        if (c == 0) atomicAdd(&g_pcnt[g], 1.0f);
    }
}

__global__ __launch_bounds__(256) void pool_final(float* __restrict__ out) {
    const int idx = blockIdx.x * 256 + threadIdx.x;
    const int g = idx >> 8;
    const float cnt = fmaxf(g_pcnt[g], 1.0f);
    out[idx] = g_psum[idx] / cnt;
}

// ---------------- launch ----------------
extern "C" void kernel_launch(void* const* d_in, const int* in_sizes, int n_in,
                              void* d_out, int out_size)
{
    const float*      x     = (const float*)d_in[0];
    const float*      ea    = (const float*)d_in[1];
    const long long*  eidx  = (const long long*)d_in[2];
    const long long*  batch = (const long long*)d_in[3];
    const float*      we1   = (const float*)d_in[4];
    const float*      be1   = (const float*)d_in[5];
    const float*      we2   = (const float*)d_in[6];
    const float*      be2   = (const float*)d_in[7];
    const float*      l0_lw = (const float*)d_in[8];
    const float*      l0_lb = (const float*)d_in[9];
    const float*      l0_w1 = (const float*)d_in[10];
    const float*      l0_b1 = (const float*)d_in[11];
    const float*      l0_w2 = (const float*)d_in[12];
    const float*      l0_b2 = (const float*)d_in[13];
    const float*      l1_lw = (const float*)d_in[14];
    const float*      l1_lb = (const float*)d_in[15];
    const float*      l1_w1 = (const float*)d_in[16];
    const float*      l1_b1 = (const float*)d_in[17];
    const float*      l1_w2 = (const float*)d_in[18];
    const float*      l1_b2 = (const float*)d_in[19];
    float* out = (float*)d_out;

    cudaFuncSetAttribute(edge_mma<0>, cudaFuncAttributeMaxDynamicSharedMemorySize,
                         EdgeSmem<0>::BYTES);
    cudaFuncSetAttribute(edge_mma<1>, cudaFuncAttributeMaxDynamicSharedMemorySize,
                         EdgeSmem<1>::BYTES);
    cudaFuncSetAttribute(node_mma<0>, cudaFuncAttributeMaxDynamicSharedMemorySize,
                         NodeSmem<0>::BYTES);
    cudaFuncSetAttribute(node_mma<1>, cudaFuncAttributeMaxDynamicSharedMemorySize,
                         NodeSmem<1>::BYTES);
    cudaFuncSetAttribute(node_mma<2>, cudaFuncAttributeMaxDynamicSharedMemorySize,
                         NodeSmem<2>::BYTES);
    cudaFuncSetAttribute(node_mma<3>, cudaFuncAttributeMaxDynamicSharedMemorySize,
                         NodeSmem<3>::BYTES);

    const int node_blocks = (NN + 63) / 64;

    // edge_mma<0> must remain the 4th launch (ncu capture target)
    zero_kernel<<<NN * HID / 256, 256>>>(eidx, l0_w1, l0_w2, l1_w1, l1_w2);   // 1
    prep_wc<0><<<HID / 8, 256>>>(we2, l0_lw, be2, l0_lb);                     // 2
    prep_wc<1><<<HID / 8, 256>>>(we2, l1_lw, be2, l1_lb);                     // 3

    // ---- layer 0 ----
    edge_mma<0><<<EE / 64, 256, EdgeSmem<0>::BYTES>>>(ea, eidx, we1, be1, x); // 4
    node_mma<0><<<node_blocks, 256, NodeSmem<0>::BYTES>>>(x, l0_b1);
    node_mma<1><<<node_blocks, 256, NodeSmem<1>::BYTES>>>(nullptr, l0_b2);

    // ---- layer 1 ----
    edge_mma<1><<<EE / 64, 256, EdgeSmem<1>::BYTES>>>(ea, eidx, we1, be1, nullptr);
    node_mma<2><<<node_blocks, 256, NodeSmem<2>::BYTES>>>(nullptr, l1_b1);
    node_mma<3><<<node_blocks, 256, NodeSmem<3>::BYTES>>>(nullptr, l1_b2);

    // ---- global mean pool ----
    pool_sum<<<NN * HID / 4 / 256, 256>>>(batch);
    pool_final<<<GG * HID / 256, 256>>>(out);
}

// round 16
// speedup vs baseline: 1.9868x; 1.2675x over previous
#include <cuda_runtime.h>
#include <cuda_fp16.h>
#include <cstdint>

#define NN   10000
#define EE   320000
#define GG   64
#define NIN  64
#define EIN  16
#define HID  256

// ---------------- scratch (device-side only; NEVER passed from host) ----------------
__device__ __align__(16) uint32_t g_W0ch[(HID / 2) * NIN];   // half2 we2@l0_lw [kpair][n]
__device__ __align__(16) uint32_t g_W1ch[(HID / 2) * HID];   // half2 we2@l1_lw
__device__ __align__(16) uint32_t g_Wp0[(NIN / 2) * HID];    // half2 l0_w1
__device__ __align__(16) uint32_t g_Wp1[(HID / 2) * HID];    // half2 l0_w2
__device__ __align__(16) uint32_t g_Wp2[(HID / 2) * HID];    // half2 l1_w1
__device__ __align__(16) uint32_t g_Wp3[(HID / 2) * HID];    // half2 l1_w2
__device__ __align__(16) float g_c0[NIN];
__device__ __align__(16) float g_c1[HID];
__device__ __align__(16) float g_agg0[NN * NIN];
__device__ __align__(16) float g_agg1[NN * HID];
__device__ __align__(16) float g_t0[NN * HID];
__device__ __align__(16) float g_x1[NN * HID];
__device__ __align__(16) float g_psum[GG * HID];
__device__ float g_pcnt[GG];
__device__ int   g_is64;

// ---------------- helpers ----------------
__device__ __forceinline__ int load_idx(const void* p, long long i) {
    if (g_is64) return (int)((const long long*)p)[i];
    return ((const int*)p)[i];
}

__device__ __forceinline__ void red_add_v4(float* p, float a, float b, float c, float d) {
    asm volatile("red.global.add.v4.f32 [%0], {%1, %2, %3, %4};"
                 :: "l"(p), "f"(a), "f"(b), "f"(c), "f"(d) : "memory");
}

__device__ __forceinline__ void red_add_v2(float* p, float a, float b) {
    asm volatile("red.global.add.v2.f32 [%0], {%1, %2};"
                 :: "l"(p), "f"(a), "f"(b) : "memory");
}

__device__ __forceinline__ uint32_t pack_h2(float lo, float hi) {
    uint32_t r;
    asm("cvt.rn.f16x2.f32 %0, %1, %2;" : "=r"(r) : "f"(hi), "f"(lo));
    return r;
}

__device__ __forceinline__ float2 unpack_h2(uint32_t u) {
    return __half22float2(*reinterpret_cast<const __half2*>(&u));
}

// m16n8k16 f16 MMA, f32 accum, D += A*B
__device__ __forceinline__ void mma_f16(float* d,
    uint32_t a0, uint32_t a1, uint32_t a2, uint32_t a3,
    uint32_t b0, uint32_t b1)
{
    asm volatile(
        "mma.sync.aligned.m16n8k16.row.col.f32.f16.f16.f32 "
        "{%0,%1,%2,%3}, {%4,%5,%6,%7}, {%8,%9}, {%0,%1,%2,%3};"
        : "+f"(d[0]), "+f"(d[1]), "+f"(d[2]), "+f"(d[3])
        : "r"(a0), "r"(a1), "r"(a2), "r"(a3), "r"(b0), "r"(b1));
}

// launch 1: zero scratch + detect index width
__global__ void zero_kernel(const long long* eidx) {
    int i = blockIdx.x * 256 + threadIdx.x;   // covers NN*HID = 2.56M
    if (i < NN * NIN) g_agg0[i] = 0.f;
    if (i < NN * HID) g_agg1[i] = 0.f;
    if (i < GG * HID) g_psum[i] = 0.f;
    if (i < GG)       g_pcnt[i] = 0.f;
    if (i == 0) {
        int is64 = 1;
        #pragma unroll 1
        for (int k = 0; k < 64; k++) {
            long long v = eidx[k];
            if (v < 0 || v >= NN) { is64 = 0; break; }
        }
        g_is64 = is64;
    }
}

// launch 2: half2-pack node weights + per-graph node counts (g_is64 set by launch 1)
__global__ void pack_kernel(const long long* __restrict__ batch,
                            const float* __restrict__ w0, const float* __restrict__ w1,
                            const float* __restrict__ w2, const float* __restrict__ w3) {
    int i = blockIdx.x * 256 + threadIdx.x;   // grid covers (HID/2)*HID = 32768
    if (i < (NIN / 2) * HID) {
        const int kp = i >> 8, n = i & 255;
        g_Wp0[i] = pack_h2(w0[(2 * kp) * HID + n], w0[(2 * kp + 1) * HID + n]);
    }
    if (i < (HID / 2) * HID) {
        const int kp = i >> 8, n = i & 255;
        g_Wp1[i] = pack_h2(w1[(2 * kp) * HID + n], w1[(2 * kp + 1) * HID + n]);
        g_Wp2[i] = pack_h2(w2[(2 * kp) * HID + n], w2[(2 * kp + 1) * HID + n]);
        g_Wp3[i] = pack_h2(w3[(2 * kp) * HID + n], w3[(2 * kp + 1) * HID + n]);
    }
    if (i < NN) atomicAdd(&g_pcnt[load_idx(batch, i)], 1.0f);
}

// launch 3: BOTH layers' weight folding. blocks 0..31 -> layer1, 32..63 -> layer0.
__global__ __launch_bounds__(256) void prep_wc_all(
    const float* __restrict__ we2,
    const float* __restrict__ l0_lw, const float* __restrict__ l1_lw,
    const float* __restrict__ be2,
    const float* __restrict__ l0_lb, const float* __restrict__ l1_lb)
{
    const int layer = (blockIdx.x < 32) ? 1 : 0;
    const int blk   = blockIdx.x & 31;
    const int COUT  = layer ? HID : NIN;
    const float* lw = layer ? l1_lw : l0_lw;
    const float* lb = layer ? l1_lb : l0_lb;
    uint32_t* wch   = layer ? g_W1ch : g_W0ch;
    float*    cv    = layer ? g_c1   : g_c0;

    __shared__ float lw_s[32][256];
    __shared__ float we2_s[8][33];
    const int i0 = blk * 8;
    const int t = threadIdx.x;
    float acc[8];
    #pragma unroll
    for (int r = 0; r < 8; r++) acc[r] = 0.f;

    #pragma unroll 1
    for (int kc = 0; kc < HID; kc += 32) {
        __syncthreads();
        for (int i = t; i < 32 * COUT / 4; i += 256) {
            const int r = i / (COUT / 4), c = (i % (COUT / 4)) * 4;
            *(float4*)&lw_s[r][c] = __ldg((const float4*)&lw[(kc + r) * COUT + c]);
        }
        we2_s[t >> 5][t & 31] = we2[(i0 + (t >> 5)) * HID + kc + (t & 31)];
        __syncthreads();
        if (t < COUT) {
            #pragma unroll 4
            for (int k = 0; k < 32; k++) {
                const float wv = lw_s[k][t];
                #pragma unroll
                for (int r = 0; r < 8; r++) acc[r] = fmaf(we2_s[r][k], wv, acc[r]);
            }
        }
    }
    if (t < COUT) {
        #pragma unroll
        for (int j = 0; j < 4; j++)
            wch[(i0 / 2 + j) * COUT + t] = pack_h2(acc[2 * j], acc[2 * j + 1]);
        if (blk == 0) {
            float a = lb[t];
            #pragma unroll 4
            for (int k = 0; k < HID; k++) a = fmaf(be2[k], lw[k * COUT + t], a);
            cv[t] = a;
        }
    }
}

// ---------------- fused edge kernel, FP16 MMA, direct-LDG B fragments ----------------
// 64 edges / block, 8 warps. Phase1: h1 = relu(ea@we1+be1). Phase2: ep = h1@Wc
// with B fragments loaded straight from L1-resident packed weights (no staging,
// no per-chunk barriers). ep staged half2 into the dead h1 buffer; RED.128 scatter.
template<int LAYER>
__global__ __launch_bounds__(256) void edge_mma(
    const float* __restrict__ ea,
    const long long* __restrict__ eidx,
    const float* __restrict__ we1,
    const float* __restrict__ be1,
    const float* __restrict__ x_arg)
{
    constexpr int COUT = (LAYER == 0) ? NIN : HID;
    constexpr int EAS  = 12;
    constexpr int H1S  = 132;
    constexpr int SN1  = HID + 8;     // 264, we1 tile only
    constexpr int MW  = (COUT == 256) ? 4 : 2;
    constexpr int NT2 = (COUT == 256) ? 4 : 2;

    const uint32_t* Wch = (LAYER == 0) ? g_W0ch : g_W1ch;
    const float* cvec   = (LAYER == 0) ? g_c0  : g_c1;
    const float* xin    = (LAYER == 0) ? x_arg : g_x1;
    float*       agg    = (LAYER == 0) ? g_agg0 : g_agg1;

    extern __shared__ char smraw[];
    uint32_t* ea_s = (uint32_t*)smraw;            // 64*EAS
    uint32_t* h1_s = ea_s + 64 * EAS;             // 64*H1S (h1, then ep)
    uint32_t* Bs   = h1_s + 64 * H1S;             // 8*SN1 (we1 only)
    float*    be1_s = (float*)(Bs + 8 * SN1);     // HID
    float*    c_s   = be1_s + HID;                // COUT
    int*      src_s = (int*)(c_s + COUT);         // 64
    int*      dst_s = src_s + 64;                 // 64

    const int t  = threadIdx.x;
    const long long e0 = (long long)blockIdx.x * 64;

    {
        const int e = t >> 2, c = (t & 3) * 4;
        const float4 v = *(const float4*)&ea[(e0 + e) * EIN + c];
        ea_s[e * EAS + (c >> 1)]     = pack_h2(v.x, v.y);
        ea_s[e * EAS + (c >> 1) + 1] = pack_h2(v.z, v.w);
    }
    if (t < 64)       src_s[t]      = load_idx(eidx, e0 + t);
    else if (t < 128) dst_s[t - 64] = load_idx(eidx, (long long)EE + e0 + (t - 64));
    be1_s[t] = be1[t];
    if (t < COUT) c_s[t] = cvec[t];
    for (int i = t; i < 8 * HID; i += 256) {
        const int kp = i >> 8, n = i & 255;
        Bs[kp * SN1 + n] = pack_h2(__ldg(&we1[(2 * kp) * HID + n]),
                                   __ldg(&we1[(2 * kp + 1) * HID + n]));
    }
    __syncthreads();

    const int w  = t >> 5, l = t & 31;
    const int lq = l >> 2, lr = l & 3;

    float d[4][4][4];

    // ---- phase 1: h1 = relu(ea @ we1 + be1); warp n-slice = w*32 ----
    {
        #pragma unroll
        for (int m = 0; m < 4; m++)
            #pragma unroll
            for (int nt = 0; nt < 4; nt++)
                { d[m][nt][0] = d[m][nt][1] = d[m][nt][2] = d[m][nt][3] = 0.f; }

        uint32_t bf[4][2];
        #pragma unroll
        for (int nt = 0; nt < 4; nt++) {
            const int n = w * 32 + nt * 8 + lq;
            bf[nt][0] = Bs[lr * SN1 + n];
            bf[nt][1] = Bs[(lr + 4) * SN1 + n];
        }
        #pragma unroll
        for (int m = 0; m < 4; m++) {
            const int row = m * 16 + lq;
            const uint32_t a0 = ea_s[row * EAS + lr];
            const uint32_t a1 = ea_s[(row + 8) * EAS + lr];
            const uint32_t a2 = ea_s[row * EAS + lr + 4];
            const uint32_t a3 = ea_s[(row + 8) * EAS + lr + 4];
            #pragma unroll
            for (int nt = 0; nt < 4; nt++)
                mma_f16(d[m][nt], a0, a1, a2, a3, bf[nt][0], bf[nt][1]);
        }
        #pragma unroll
        for (int m = 0; m < 4; m++) {
            const int row = m * 16 + lq;
            #pragma unroll
            for (int nt = 0; nt < 4; nt++) {
                const int p = w * 16 + nt * 4 + lr;
                const float bv0 = be1_s[2 * p], bv1 = be1_s[2 * p + 1];
                h1_s[row * H1S + p] =
                    pack_h2(fmaxf(d[m][nt][0] + bv0, 0.f), fmaxf(d[m][nt][1] + bv1, 0.f));
                h1_s[(row + 8) * H1S + p] =
                    pack_h2(fmaxf(d[m][nt][2] + bv0, 0.f), fmaxf(d[m][nt][3] + bv1, 0.f));
            }
        }
    }
    __syncthreads();   // h1 visible to all warps

    // ---- phase 2: ep = h1 @ Wc; B fragments via direct LDG (L1-resident weights) ----
    const int mg = (COUT == 256) ? 0 : (w & 1);
    const int n2 = (COUT == 256) ? w * 32 : (w >> 1) * 16;
    #pragma unroll
    for (int m = 0; m < MW; m++)
        #pragma unroll
        for (int nt = 0; nt < NT2; nt++)
            { d[m][nt][0] = d[m][nt][1] = d[m][nt][2] = d[m][nt][3] = 0.f; }

    #pragma unroll 4
    for (int kp8 = 0; kp8 < HID / 16; kp8++) {
        const int pb = kp8 * 8;
        uint32_t bf[NT2][2];
        #pragma unroll
        for (int nt = 0; nt < NT2; nt++) {
            const int n = n2 + nt * 8 + lq;
            bf[nt][0] = __ldg(&Wch[(size_t)(pb + lr) * COUT + n]);
            bf[nt][1] = __ldg(&Wch[(size_t)(pb + lr + 4) * COUT + n]);
        }
        #pragma unroll
        for (int m = 0; m < MW; m++) {
            const int row = mg * 32 + m * 16 + lq;
            const uint32_t a0 = h1_s[row * H1S + pb + lr];
            const uint32_t a1 = h1_s[(row + 8) * H1S + pb + lr];
            const uint32_t a2 = h1_s[row * H1S + pb + lr + 4];
            const uint32_t a3 = h1_s[(row + 8) * H1S + pb + lr + 4];
            #pragma unroll
            for (int nt = 0; nt < NT2; nt++)
                mma_f16(d[m][nt], a0, a1, a2, a3, bf[nt][0], bf[nt][1]);
        }
    }

    __syncthreads();   // all h1 reads done; reuse h1_s as half2 ep storage
    #pragma unroll
    for (int m = 0; m < MW; m++) {
        const int row = mg * 32 + m * 16 + lq;
        #pragma unroll
        for (int nt = 0; nt < NT2; nt++) {
            const int p = (n2 >> 1) + nt * 4 + lr;
            h1_s[row * H1S + p]       = pack_h2(d[m][nt][0], d[m][nt][1]);
            h1_s[(row + 8) * H1S + p] = pack_h2(d[m][nt][2], d[m][nt][3]);
        }
    }
    __syncthreads();

    constexpr int CG = COUT / 4;
    for (int i = t; i < 64 * CG; i += 256) {
        const int e = i / CG, c = (i % CG) * 4;
        const float2 e01 = unpack_h2(h1_s[e * H1S + (c >> 1)]);
        const float2 e23 = unpack_h2(h1_s[e * H1S + (c >> 1) + 1]);
        const float4 xv = __ldg((const float4*)&xin[(size_t)src_s[e] * COUT + c]);
        const float4 cv = *(const float4*)&c_s[c];
        red_add_v4(&agg[(size_t)dst_s[e] * COUT + c],
                   fmaxf(xv.x + e01.x + cv.x, 0.f),
                   fmaxf(xv.y + e01.y + cv.y, 0.f),
                   fmaxf(xv.z + e23.x + cv.z, 0.f),
                   fmaxf(xv.w + e23.y + cv.w, 0.f));
    }
}

template<int LAYER> struct EdgeSmem {
    static constexpr int COUT = (LAYER == 0) ? NIN : HID;
    static constexpr int BYTES =
        (64 * 12 + 64 * 132 + 8 * (HID + 8)) * 4
        + HID * 4 + COUT * 4 + 128 * 4;
};

// ---------------- node MLP via FP16 MMA, direct-LDG B fragments ----------------
// MODE 0: A=x (K=64) +g_agg0 -> g_t0 ; MODE 1: A=g_t0 -> g_x1
// MODE 2: A=g_x1 +g_agg1 -> g_t0     ; MODE 3: A=g_t0 -> RED into g_psum (pool fused)
template<int MODE>
__global__ __launch_bounds__(256) void node_mma(
    const float* __restrict__ x_arg,
    const float* __restrict__ b,
    const long long* __restrict__ batch)
{
    constexpr int  K   = (MODE == 0) ? NIN : HID;
    constexpr bool ADD = (MODE == 0) || (MODE == 2);
    constexpr int  KP  = K / 2;
    constexpr int  AS  = KP + 4;
    const float* A  = (MODE == 0) ? x_arg :
                      (MODE == 2) ? g_x1  : g_t0;
    const float* A2 = (MODE == 0) ? g_agg0 : g_agg1;
    const uint32_t* Wp = (MODE == 0) ? g_Wp0 : (MODE == 1) ? g_Wp1 :
                         (MODE == 2) ? g_Wp2 : g_Wp3;
    float*       C  = (MODE == 1) ? g_x1 : g_t0;

    extern __shared__ char smraw[];
    uint32_t* a_s = (uint32_t*)smraw;          // 64*AS
    float*    b_s = (float*)(a_s + 64 * AS);   // HID
    int*      gb_s = (int*)(b_s + HID);        // 64 (MODE 3 only)

    const int t  = threadIdx.x;
    const int r0 = blockIdx.x * 64;

    for (int i = t; i < 64 * K / 4; i += 256) {
        const int r = i / (K / 4), c = (i % (K / 4)) * 4;
        float4 v = make_float4(0.f, 0.f, 0.f, 0.f);
        if (r0 + r < NN) {
            v = *(const float4*)&A[(size_t)(r0 + r) * K + c];
            if (ADD) {
                const float4 u = *(const float4*)&A2[(size_t)(r0 + r) * K + c];
                v.x += u.x; v.y += u.y; v.z += u.z; v.w += u.w;
            }
        }
        a_s[r * AS + (c >> 1)]     = pack_h2(v.x, v.y);
        a_s[r * AS + (c >> 1) + 1] = pack_h2(v.z, v.w);
    }
    b_s[t] = b[t];
    if (MODE == 3 && t < 64)
        gb_s[t] = (r0 + t < NN) ? load_idx(batch, r0 + t) : 0;
    __syncthreads();

    const int w  = t >> 5, l = t & 31;
    const int lq = l >> 2, lr = l & 3;

    float d[4][4][4];
    #pragma unroll
    for (int m = 0; m < 4; m++)
        #pragma unroll
        for (int nt = 0; nt < 4; nt++)
            { d[m][nt][0] = d[m][nt][1] = d[m][nt][2] = d[m][nt][3] = 0.f; }

    #pragma unroll 4
    for (int kp8 = 0; kp8 < K / 16; kp8++) {
        const int pb = kp8 * 8;
        uint32_t bf[4][2];
        #pragma unroll
        for (int nt = 0; nt < 4; nt++) {
            const int n = w * 32 + nt * 8 + lq;
            bf[nt][0] = __ldg(&Wp[(size_t)(pb + lr) * HID + n]);
            bf[nt][1] = __ldg(&Wp[(size_t)(pb + lr + 4) * HID + n]);
        }
        #pragma unroll
        for (int m = 0; m < 4; m++) {
            const int row = m * 16 + lq;
            const uint32_t a0 = a_s[row * AS + pb + lr];
            const uint32_t a1 = a_s[(row + 8) * AS + pb + lr];
            const uint32_t a2 = a_s[row * AS + pb + lr + 4];
            const uint32_t a3 = a_s[(row + 8) * AS + pb + lr + 4];
            #pragma unroll
            for (int nt = 0; nt < 4; nt++)
                mma_f16(d[m][nt], a0, a1, a2, a3, bf[nt][0], bf[nt][1]);
        }
    }

    // epilogue: bias + relu; MODE 3 pools directly into g_psum
    #pragma unroll
    for (int m = 0; m < 4; m++) {
        #pragma unroll
        for (int nt = 0; nt < 4; nt++) {
            const int n = w * 32 + nt * 8 + 2 * lr;
            const float bv0 = b_s[n], bv1 = b_s[n + 1];
            const int row0 = r0 + m * 16 + lq;
            const int row1 = row0 + 8;
            const float v00 = fmaxf(d[m][nt][0] + bv0, 0.f);
            const float v01 = fmaxf(d[m][nt][1] + bv1, 0.f);
            const float v10 = fmaxf(d[m][nt][2] + bv0, 0.f);
            const float v11 = fmaxf(d[m][nt][3] + bv1, 0.f);
            if (MODE == 3) {
                if (row0 < NN)
                    red_add_v2(&g_psum[gb_s[m * 16 + lq] * HID + n], v00, v01);
                if (row1 < NN)
                    red_add_v2(&g_psum[gb_s[m * 16 + lq + 8] * HID + n], v10, v11);
            } else {
                if (row0 < NN)
                    *(float2*)&C[(size_t)row0 * HID + n] = make_float2(v00, v01);
                if (row1 < NN)
                    *(float2*)&C[(size_t)row1 * HID + n] = make_float2(v10, v11);
            }
        }
    }
}

template<int MODE> struct NodeSmem {
    static constexpr int K  = (MODE == 0) ? NIN : HID;
    static constexpr int AS = K / 2 + 4;
    static constexpr int BYTES = (64 * AS) * 4 + HID * 4 + 64 * 4;
};

// ---------------- pool finalize ----------------
__global__ __launch_bounds__(256) void pool_final(float* __restrict__ out) {
    const int idx = blockIdx.x * 256 + threadIdx.x;
    const int g = idx >> 8;
    const float cnt = fmaxf(g_pcnt[g], 1.0f);
    out[idx] = g_psum[idx] / cnt;
}

// ---------------- launch ----------------
extern "C" void kernel_launch(void* const* d_in, const int* in_sizes, int n_in,
                              void* d_out, int out_size)
{
    const float*      x     = (const float*)d_in[0];
    const float*      ea    = (const float*)d_in[1];
    const long long*  eidx  = (const long long*)d_in[2];
    const long long*  batch = (const long long*)d_in[3];
    const float*      we1   = (const float*)d_in[4];
    const float*      be1   = (const float*)d_in[5];
    const float*      we2   = (const float*)d_in[6];
    const float*      be2   = (const float*)d_in[7];
    const float*      l0_lw = (const float*)d_in[8];
    const float*      l0_lb = (const float*)d_in[9];
    const float*      l0_w1 = (const float*)d_in[10];
    const float*      l0_b1 = (const float*)d_in[11];
    const float*      l0_w2 = (const float*)d_in[12];
    const float*      l0_b2 = (const float*)d_in[13];
    const float*      l1_lw = (const float*)d_in[14];
    const float*      l1_lb = (const float*)d_in[15];
    const float*      l1_w1 = (const float*)d_in[16];
    const float*      l1_b1 = (const float*)d_in[17];
    const float*      l1_w2 = (const float*)d_in[18];
    const float*      l1_b2 = (const float*)d_in[19];
    float* out = (float*)d_out;

    cudaFuncSetAttribute(edge_mma<0>, cudaFuncAttributeMaxDynamicSharedMemorySize,
                         EdgeSmem<0>::BYTES);
    cudaFuncSetAttribute(edge_mma<1>, cudaFuncAttributeMaxDynamicSharedMemorySize,
                         EdgeSmem<1>::BYTES);
    cudaFuncSetAttribute(node_mma<0>, cudaFuncAttributeMaxDynamicSharedMemorySize,
                         NodeSmem<0>::BYTES);
    cudaFuncSetAttribute(node_mma<1>, cudaFuncAttributeMaxDynamicSharedMemorySize,
                         NodeSmem<1>::BYTES);
    cudaFuncSetAttribute(node_mma<2>, cudaFuncAttributeMaxDynamicSharedMemorySize,
                         NodeSmem<2>::BYTES);
    cudaFuncSetAttribute(node_mma<3>, cudaFuncAttributeMaxDynamicSharedMemorySize,
                         NodeSmem<3>::BYTES);

    const int node_blocks = (NN + 63) / 64;

    // edge_mma<0> must remain the 4th launch (ncu capture target)
    zero_kernel<<<NN * HID / 256, 256>>>(eidx);                               // 1
    pack_kernel<<<(HID / 2) * HID / 256, 256>>>(batch, l0_w1, l0_w2, l1_w1, l1_w2); // 2
    prep_wc_all<<<64, 256>>>(we2, l0_lw, l1_lw, be2, l0_lb, l1_lb);           // 3

    // ---- layer 0 ----
    edge_mma<0><<<EE / 64, 256, EdgeSmem<0>::BYTES>>>(ea, eidx, we1, be1, x); // 4
    node_mma<0><<<node_blocks, 256, NodeSmem<0>::BYTES>>>(x, l0_b1, nullptr);
    node_mma<1><<<node_blocks, 256, NodeSmem<1>::BYTES>>>(nullptr, l0_b2, nullptr);

    // ---- layer 1 ----
    edge_mma<1><<<EE / 64, 256, EdgeSmem<1>::BYTES>>>(ea, eidx, we1, be1, nullptr);
    node_mma<2><<<node_blocks, 256, NodeSmem<2>::BYTES>>>(nullptr, l1_b1, nullptr);
    node_mma<3><<<node_blocks, 256, NodeSmem<3>::BYTES>>>(nullptr, l1_b2, batch);

    // ---- pool finalize ----
    pool_final<<<GG * HID / 256, 256>>>(out);
}